// round 7
// baseline (speedup 1.0000x reference)
#include <cuda_runtime.h>
#include <cuda_fp16.h>
#include <cstdint>

#define NN 100000
#define EE 1600000
#define DIN_ 32
#define HH 64
#define GG 128
#define OUTC 10

#define AGG_BLOCKS 592
#define AGG_WPB 8
#define AGG_WARPS (AGG_BLOCKS * AGG_WPB)                 // 4736
#define AGG_NPER ((NN + AGG_WARPS - 1) / AGG_WARPS)      // 22

#define EPROJ_BLOCKS 444
#define NTILES (EE / 128)                                 // 12500 exact

typedef unsigned long long u64;
typedef unsigned int u32;

// ---------------- scratch ----------------
__device__ float  g_h [(size_t)NN * HH];      // layer output (pre-BN "hraw")
__device__ float  g_agg[(size_t)NN * HH];
__device__ __half g_proj[(size_t)EE * 64];    // per-layer edge projection (CSR order)
__device__ int    g_srcs[EE];                 // src permuted to CSR order
__device__ int    g_pos[EE];                  // original edge -> CSR position
__device__ int    g_rowptr[NN + 1];
__device__ int    g_cur[NN];
__device__ float  g_stats[4 * 2 * HH];
__device__ float  g_bnsc[4 * HH];
__device__ float  g_bnsf[4 * HH];
__device__ float  g_pool[GG * HH];
__device__ float  g_cnt[GG];

// ---------------- f32x2 helpers ----------------
__device__ __forceinline__ u64 ffma2(u64 a, u64 b, u64 c) {
    u64 d; asm("fma.rn.f32x2 %0, %1, %2, %3;" : "=l"(d) : "l"(a), "l"(b), "l"(c)); return d;
}
__device__ __forceinline__ u64 fmul2(u64 a, u64 b) {
    u64 d; asm("mul.rn.f32x2 %0, %1, %2;" : "=l"(d) : "l"(a), "l"(b)); return d;
}
__device__ __forceinline__ void unpk2(u64 v, float& lo, float& hi) {
    asm("mov.b64 {%0, %1}, %2;" : "=f"(lo), "=f"(hi) : "l"(v));
}

// ---------------- cp.async helpers ----------------
__device__ __forceinline__ void cp_async16(u32 saddr, const void* gaddr, int pred) {
    asm volatile(
        "{\n\t.reg .pred p;\n\tsetp.ne.b32 p, %2, 0;\n\t"
        "@p cp.async.ca.shared.global [%0], [%1], 16;\n\t}"
        :: "r"(saddr), "l"(gaddr), "r"(pred) : "memory");
}
#define CP_COMMIT() asm volatile("cp.async.commit_group;" ::: "memory")
#define CP_WAIT1()  asm volatile("cp.async.wait_group 1;" ::: "memory")
#define CP_WAIT0()  asm volatile("cp.async.wait_group 0;" ::: "memory")

// ---------------- CSR build ----------------
__global__ void hist_kernel(const int* __restrict__ eidx) {
    int e = blockIdx.x * blockDim.x + threadIdx.x;
    if (e < EE) atomicAdd(&g_cur[eidx[EE + e]], 1);
}

__global__ void __launch_bounds__(1024) scan_kernel() {
    int t = threadIdx.x;
    int sum = 0;
    if (t < 1000) {
        const int4* p = (const int4*)(g_cur + t * 100);
#pragma unroll 5
        for (int q = 0; q < 25; q++) { int4 v = p[q]; sum += v.x + v.y + v.z + v.w; }
    }
    int lane = t & 31, wid = t >> 5;
    int inc = sum;
#pragma unroll
    for (int d = 1; d < 32; d <<= 1) {
        int n = __shfl_up_sync(0xffffffffu, inc, d);
        if (lane >= d) inc += n;
    }
    __shared__ int wsum[32];
    if (lane == 31) wsum[wid] = inc;
    __syncthreads();
    if (wid == 0) {
        int wv = wsum[lane];
        int winc = wv;
#pragma unroll
        for (int d = 1; d < 32; d <<= 1) {
            int n = __shfl_up_sync(0xffffffffu, winc, d);
            if (lane >= d) winc += n;
        }
        wsum[lane] = winc - wv;
    }
    __syncthreads();
    if (t < 1000) {
        int run = inc - sum + wsum[wid];
        const int4* p = (const int4*)(g_cur + t * 100);
#pragma unroll 5
        for (int q = 0; q < 25; q++) {
            int4 v = p[q];
            int i = t * 100 + q * 4;
            int4 r; r.x = run; run += v.x; r.y = run; run += v.y;
            r.z = run; run += v.z; r.w = run; run += v.w;
            *(int4*)(g_rowptr + i) = r;
            *(int4*)(g_cur + i) = r;
        }
    }
    if (t == 1023) g_rowptr[NN] = EE;
}

__global__ void scatter_kernel(const int* __restrict__ eidx) {
    int e = blockIdx.x * blockDim.x + threadIdx.x;
    if (e >= EE) return;
    int d = eidx[EE + e];
    int pos = atomicAdd(&g_cur[d], 1);
    g_srcs[pos] = eidx[e];
    g_pos[e] = pos;
}

// ---------------- edge projection GEMM: proj[pos[e]] = ea[e] @ ew^T + eb (fp16) ----
template <int C>
__global__ void __launch_bounds__(256) eproj_kernel(
    const float* __restrict__ ea, const int* __restrict__ posv,
    const float* __restrict__ ew, const float* __restrict__ ebv,
    __half* __restrict__ proj)
{
    constexpr int CW = C / 8;                 // channels per thread (8 or 4)
    __shared__ __align__(16) float B_s[C * 16];
    __shared__ float bias_s[C];
    __shared__ __align__(16) float A_s[2][128 * 16];
    __shared__ __align__(16) int pos_s[2][128];

    int t = threadIdx.x;
    for (int i = t; i < C * 16; i += 256) B_s[i] = ew[i];
    if (t < C) bias_s[t] = ebv[t];
    int tx = t & 7, ty = t >> 3;              // tx: channel group, ty: 4 edges

    u32 sA[2] = { (u32)__cvta_generic_to_shared(&A_s[0][0]),
                  (u32)__cvta_generic_to_shared(&A_s[1][0]) };
    u32 sP[2] = { (u32)__cvta_generic_to_shared(&pos_s[0][0]),
                  (u32)__cvta_generic_to_shared(&pos_s[1][0]) };

    int tile = blockIdx.x;
    if (tile < NTILES) {
        cp_async16(sA[0] + t * 32,      ea + (size_t)tile * 2048 + t * 8, 1);
        cp_async16(sA[0] + t * 32 + 16, ea + (size_t)tile * 2048 + t * 8 + 4, 1);
        cp_async16(sP[0] + t * 16, posv + tile * 128 + t * 4, t < 32);
    }
    CP_COMMIT();
    __syncthreads();

    int b = 0;
    while (tile < NTILES) {
        int ntile = tile + gridDim.x;
        if (ntile < NTILES) {
            cp_async16(sA[b ^ 1] + t * 32,      ea + (size_t)ntile * 2048 + t * 8, 1);
            cp_async16(sA[b ^ 1] + t * 32 + 16, ea + (size_t)ntile * 2048 + t * 8 + 4, 1);
            cp_async16(sP[b ^ 1] + t * 16, posv + ntile * 128 + t * 4, t < 32);
        }
        CP_COMMIT();
        CP_WAIT1();
        __syncthreads();

        const float* A = &A_s[b][0];
#pragma unroll
        for (int ep = 0; ep < 2; ep++) {      // 2 passes of 2 edges each
            int e0 = ty * 4 + ep * 2;
            ulonglong2 a0[4], a1[4];
            const float* Ar0 = &A[e0 * 16];
            const float* Ar1 = Ar0 + 16;
#pragma unroll
            for (int q = 0; q < 4; q++) {
                a0[q] = *(const ulonglong2*)&Ar0[q * 4];
                a1[q] = *(const ulonglong2*)&Ar1[q * 4];
            }
            float v0s[CW], v1s[CW];
#pragma unroll
            for (int cc = 0; cc < CW; cc++) {
                int c = tx * CW + cc;
                ulonglong2 w0 = *(const ulonglong2*)&B_s[c * 16];
                ulonglong2 w1 = *(const ulonglong2*)&B_s[c * 16 + 4];
                ulonglong2 w2 = *(const ulonglong2*)&B_s[c * 16 + 8];
                ulonglong2 w3 = *(const ulonglong2*)&B_s[c * 16 + 12];
                u64 acc0 = fmul2(a0[0].x, w0.x);
                acc0 = ffma2(a0[0].y, w0.y, acc0);
                acc0 = ffma2(a0[1].x, w1.x, acc0);
                acc0 = ffma2(a0[1].y, w1.y, acc0);
                acc0 = ffma2(a0[2].x, w2.x, acc0);
                acc0 = ffma2(a0[2].y, w2.y, acc0);
                acc0 = ffma2(a0[3].x, w3.x, acc0);
                acc0 = ffma2(a0[3].y, w3.y, acc0);
                u64 acc1 = fmul2(a1[0].x, w0.x);
                acc1 = ffma2(a1[0].y, w0.y, acc1);
                acc1 = ffma2(a1[1].x, w1.x, acc1);
                acc1 = ffma2(a1[1].y, w1.y, acc1);
                acc1 = ffma2(a1[2].x, w2.x, acc1);
                acc1 = ffma2(a1[2].y, w2.y, acc1);
                acc1 = ffma2(a1[3].x, w3.x, acc1);
                acc1 = ffma2(a1[3].y, w3.y, acc1);
                float l0, h0, l1, h1;
                unpk2(acc0, l0, h0); unpk2(acc1, l1, h1);
                float bb = bias_s[c];
                v0s[cc] = l0 + h0 + bb;
                v1s[cc] = l1 + h1 + bb;
            }
            int p0 = pos_s[b][e0], p1 = pos_s[b][e0 + 1];
            u32 r0[CW / 2], r1[CW / 2];
#pragma unroll
            for (int k = 0; k < CW / 2; k++) {
                __half2 h0 = __floats2half2_rn(v0s[2 * k], v0s[2 * k + 1]);
                __half2 h1 = __floats2half2_rn(v1s[2 * k], v1s[2 * k + 1]);
                r0[k] = *reinterpret_cast<u32*>(&h0);
                r1[k] = *reinterpret_cast<u32*>(&h1);
            }
            if (CW == 8) {
                *(uint4*)(proj + (size_t)p0 * C + tx * CW) = make_uint4(r0[0], r0[1], r0[2], r0[3]);
                *(uint4*)(proj + (size_t)p1 * C + tx * CW) = make_uint4(r1[0], r1[1], r1[2], r1[3]);
            } else {
                *(uint2*)(proj + (size_t)p0 * C + tx * CW) = make_uint2(r0[0], r0[1]);
                *(uint2*)(proj + (size_t)p1 * C + tx * CW) = make_uint2(r1[0], r1[1]);
            }
        }
        __syncthreads();
        tile = ntile; b ^= 1;
    }
}

// ---------------- layer-0 aggregation (C=32): lite streaming ----------------
__global__ void __launch_bounds__(256) agg32_kernel(
    const float* __restrict__ xin, const __half* __restrict__ proj,
    float* __restrict__ agg)
{
    int wip = threadIdx.x >> 5, lane = threadIdx.x & 31;
    int w = blockIdx.x * AGG_WPB + wip;
    int nbeg = w * AGG_NPER;
    if (nbeg >= NN) return;
    int nend = nbeg + AGG_NPER; if (nend > NN) nend = NN;

    int jbeg = g_rowptr[nbeg], jend = g_rowptr[nend];
    int node = nbeg;
    int next_end = g_rowptr[node + 1];
    float self = xin[(size_t)node * 32 + lane];
    float A = 0.f;

    for (int j0 = jbeg; j0 < jend; j0 += 8) {
        int m = jend - j0; if (m > 8) m = 8;
        float xs[8]; __half pr[8];
#pragma unroll
        for (int e = 0; e < 8; e++) {
            if (e < m) {
                int s = g_srcs[j0 + e];
                xs[e] = xin[(size_t)s * 32 + lane];
                pr[e] = proj[(size_t)(j0 + e) * 32 + lane];
            }
        }
#pragma unroll
        for (int e = 0; e < 8; e++) {
            if (e < m) {
                int j = j0 + e;
                while (j >= next_end) {               // uniform across warp
                    agg[(size_t)node * 32 + lane] = self + A;
                    A = 0.f;
                    node++;
                    next_end = g_rowptr[node + 1];
                    self = xin[(size_t)node * 32 + lane];
                }
                A += fmaxf(xs[e] + __half2float(pr[e]), 0.f);
            }
        }
    }
    while (true) {
        agg[(size_t)node * 32 + lane] = self + A;
        A = 0.f;
        node++;
        if (node >= nend) break;
        self = xin[(size_t)node * 32 + lane];
    }
}

// ---------------- layers 1-3 aggregation (C=64, BN+relu folded): lite -------------
__global__ void __launch_bounds__(256) agg64_kernel(
    const float* __restrict__ hraw, const __half2* __restrict__ proj2,
    const float* __restrict__ bnsc, const float* __restrict__ bnsf,
    float* __restrict__ agg)
{
    int wip = threadIdx.x >> 5, lane = threadIdx.x & 31;
    int w = blockIdx.x * AGG_WPB + wip;
    int nbeg = w * AGG_NPER;
    if (nbeg >= NN) return;
    int nend = nbeg + AGG_NPER; if (nend > NN) nend = NN;
    int c0 = lane * 2;
    float sc0 = bnsc[c0], sc1 = bnsc[c0 + 1];
    float sf0 = bnsf[c0], sf1 = bnsf[c0 + 1];

    int jbeg = g_rowptr[nbeg], jend = g_rowptr[nend];
    int node = nbeg;
    int next_end = g_rowptr[node + 1];
    float2 self = *(const float2*)(hraw + (size_t)node * 64 + c0);
    float A0 = 0.f, A1 = 0.f;

    for (int j0 = jbeg; j0 < jend; j0 += 8) {
        int m = jend - j0; if (m > 8) m = 8;
        float2 xs[8]; __half2 pr[8];
#pragma unroll
        for (int e = 0; e < 8; e++) {
            if (e < m) {
                int s = g_srcs[j0 + e];
                xs[e] = *(const float2*)(hraw + (size_t)s * 64 + c0);
                pr[e] = proj2[(size_t)(j0 + e) * 32 + lane];
            }
        }
#pragma unroll
        for (int e = 0; e < 8; e++) {
            if (e < m) {
                int j = j0 + e;
                while (j >= next_end) {               // uniform across warp
                    float2 o;
                    o.x = fmaxf(fmaf(self.x, sc0, sf0), 0.f) + A0;
                    o.y = fmaxf(fmaf(self.y, sc1, sf1), 0.f) + A1;
                    *(float2*)(agg + (size_t)node * 64 + c0) = o;
                    A0 = A1 = 0.f;
                    node++;
                    next_end = g_rowptr[node + 1];
                    self = *(const float2*)(hraw + (size_t)node * 64 + c0);
                }
                float2 p = __half22float2(pr[e]);
                float x0 = fmaxf(fmaf(xs[e].x, sc0, sf0), 0.f);
                float x1 = fmaxf(fmaf(xs[e].y, sc1, sf1), 0.f);
                A0 += fmaxf(x0 + p.x, 0.f);
                A1 += fmaxf(x1 + p.y, 0.f);
            }
        }
    }
    while (true) {
        float2 o;
        o.x = fmaxf(fmaf(self.x, sc0, sf0), 0.f) + A0;
        o.y = fmaxf(fmaf(self.y, sc1, sf1), 0.f) + A1;
        *(float2*)(agg + (size_t)node * 64 + c0) = o;
        A0 = A1 = 0.f;
        node++;
        if (node >= nend) break;
        self = *(const float2*)(hraw + (size_t)node * 64 + c0);
    }
}

// ---------------- fused node MLP + BN stats ----------------
template <int K>
__global__ void __launch_bounds__(256) gemm_fused_kernel(
    const float* __restrict__ in, const float* __restrict__ w1,
    const float* __restrict__ b1, const float* __restrict__ w2,
    const float* __restrict__ b2, float* __restrict__ out,
    float* __restrict__ stats)
{
    __shared__ __align__(16) float a_s[64][K + 4];
    __shared__ __align__(16) float w_s[64][68];
    __shared__ __align__(16) float h_s[64][68];
    constexpr int K4 = K / 4;
    int t = threadIdx.x;
    int n0 = blockIdx.x * 64;
    int tx = t & 15, ty = t >> 4;

    for (int i = t; i < 64 * K4; i += 256) {
        int r = i / K4, c4 = i % K4;
        *(float4*)&w_s[r][c4 * 4] = ((const float4*)w1)[i];
        int n = n0 + r;
        float4 v = (n < NN) ? ((const float4*)in)[(size_t)n * K4 + c4] : make_float4(0.f,0.f,0.f,0.f);
        *(float4*)&a_s[r][c4 * 4] = v;
    }
    __syncthreads();

    {
        u64 acc2[4][4] = {};
#pragma unroll
        for (int k = 0; k < K; k += 4) {
            ulonglong2 a[4], b[4];
#pragma unroll
            for (int i = 0; i < 4; i++) a[i] = *(const ulonglong2*)&a_s[ty * 4 + i][k];
#pragma unroll
            for (int j = 0; j < 4; j++) b[j] = *(const ulonglong2*)&w_s[tx + j * 16][k];
#pragma unroll
            for (int i = 0; i < 4; i++)
#pragma unroll
                for (int j = 0; j < 4; j++)
                    acc2[i][j] = ffma2(a[i].x, b[j].x, ffma2(a[i].y, b[j].y, acc2[i][j]));
        }
#pragma unroll
        for (int j = 0; j < 4; j++) {
            int c = tx + j * 16;
            float bb = b1[c];
#pragma unroll
            for (int i = 0; i < 4; i++) {
                float lo, hi; unpk2(acc2[i][j], lo, hi);
                h_s[ty * 4 + i][c] = fmaxf(lo + hi + bb, 0.f);
            }
        }
    }
    __syncthreads();
    for (int i = t; i < 64 * 16; i += 256) {
        int r = i >> 4, c4 = i & 15;
        *(float4*)&w_s[r][c4 * 4] = ((const float4*)w2)[i];
    }
    __syncthreads();

    float val[4][4];
    {
        u64 acc2[4][4] = {};
#pragma unroll
        for (int k = 0; k < 64; k += 4) {
            ulonglong2 a[4], b[4];
#pragma unroll
            for (int i = 0; i < 4; i++) a[i] = *(const ulonglong2*)&h_s[ty * 4 + i][k];
#pragma unroll
            for (int j = 0; j < 4; j++) b[j] = *(const ulonglong2*)&w_s[tx + j * 16][k];
#pragma unroll
            for (int i = 0; i < 4; i++)
#pragma unroll
                for (int j = 0; j < 4; j++)
                    acc2[i][j] = ffma2(a[i].x, b[j].x, ffma2(a[i].y, b[j].y, acc2[i][j]));
        }
#pragma unroll
        for (int j = 0; j < 4; j++) {
            int c = tx + j * 16;
            float bb = b2[c];
#pragma unroll
            for (int i = 0; i < 4; i++) {
                float lo, hi; unpk2(acc2[i][j], lo, hi);
                val[i][j] = fmaxf(lo + hi + bb, 0.f);
            }
        }
    }
    __syncthreads();

    float* redS = &a_s[0][0];
    float* redQ = &h_s[0][0];
#pragma unroll
    for (int j = 0; j < 4; j++) {
        int c = tx + j * 16;
        float s = 0.f, q = 0.f;
#pragma unroll
        for (int i = 0; i < 4; i++) {
            int n = n0 + ty * 4 + i;
            if (n < NN) {
                float v = val[i][j];
                out[(size_t)n * 64 + c] = v;
                s += v; q = fmaf(v, v, q);
            }
        }
        redS[ty * 64 + c] = s;
        redQ[ty * 64 + c] = q;
    }
    __syncthreads();
    if (t < 64) {
        float S = 0.f, Q = 0.f;
#pragma unroll
        for (int r = 0; r < 16; r++) { S += redS[r * 64 + t]; Q += redQ[r * 64 + t]; }
        atomicAdd(&stats[t], S);
        atomicAdd(&stats[64 + t], Q);
    }
}

// ---------------- BN coefficients ----------------
__global__ void bn_coef_kernel(const float* __restrict__ stats,
                               const float* __restrict__ gamma, const float* __restrict__ beta,
                               float* __restrict__ sc, float* __restrict__ sf) {
    int t = threadIdx.x;
    float mu = stats[t] * (1.0f / NN);
    float var = stats[64 + t] * (1.0f / NN) - mu * mu;
    float inv = rsqrtf(var + 1e-5f);
    float g = gamma[t], b = beta[t];
    sc[t] = inv * g;
    sf[t] = b - mu * inv * g;
}

// ---------------- pool (BN of last layer folded; batch sorted) ----------------
__global__ void pool_kernel(const float* __restrict__ hraw, const int* __restrict__ batch,
                            const float* __restrict__ bnsc, const float* __restrict__ bnsf) {
    int warp = blockIdx.x * (blockDim.x >> 5) + (threadIdx.x >> 5);
    int lane = threadIdx.x & 31;
    int base = warp * 32;
    if (base >= NN) return;
    int end = min(base + 32, NN);
    int c0 = lane * 2;
    float sc0 = bnsc[c0], sc1 = bnsc[c0 + 1];
    float sf0 = bnsf[c0], sf1 = bnsf[c0 + 1];

    int curb = batch[base];
    float a0 = 0.f, a1 = 0.f, cf = 0.f;
    for (int n = base; n < end; n++) {
        int b = batch[n];
        if (b != curb) {
            atomicAdd(&g_pool[curb * 64 + c0], a0);
            atomicAdd(&g_pool[curb * 64 + c0 + 1], a1);
            if (lane == 0) atomicAdd(&g_cnt[curb], cf);
            a0 = a1 = cf = 0.f;
            curb = b;
        }
        float2 v = *(const float2*)(hraw + (size_t)n * 64 + c0);
        a0 += fmaxf(fmaf(v.x, sc0, sf0), 0.f);
        a1 += fmaxf(fmaf(v.y, sc1, sf1), 0.f);
        cf += 1.f;
    }
    atomicAdd(&g_pool[curb * 64 + c0], a0);
    atomicAdd(&g_pool[curb * 64 + c0 + 1], a1);
    if (lane == 0) atomicAdd(&g_cnt[curb], cf);
}

// ---------------- MLP head ----------------
__global__ void head_kernel(const float* __restrict__ hw1, const float* __restrict__ hb1,
                            const float* __restrict__ hw2, const float* __restrict__ hb2,
                            float* __restrict__ out) {
    int g = blockIdx.x, t = threadIdx.x;
    __shared__ float p[64];
    __shared__ float z[128];
    if (t < 64) {
        float c = g_cnt[g];
        p[t] = g_pool[g * 64 + t] / fmaxf(c, 1.0f);
    }
    __syncthreads();
    float s = hb1[t];
#pragma unroll 8
    for (int k = 0; k < 64; k++) s = fmaf(p[k], hw1[t * 64 + k], s);
    z[t] = fmaxf(s, 0.f);
    __syncthreads();
    if (t < OUTC) {
        float s2 = hb2[t];
#pragma unroll 8
        for (int k = 0; k < 128; k++) s2 = fmaf(z[k], hw2[t * 128 + k], s2);
        out[g * OUTC + t] = s2;
    }
}

// ---------------- launch ----------------
extern "C" void kernel_launch(void* const* d_in, const int* in_sizes, int n_in,
                              void* d_out, int out_size) {
    const float* x     = (const float*)d_in[0];
    const int*   eidx  = (const int*)  d_in[1];
    const float* ea    = (const float*)d_in[2];
    const int*   batch = (const int*)  d_in[3];
    const float* l0_ew = (const float*)d_in[4];
    const float* l0_eb = (const float*)d_in[5];
    const float* l0_w1 = (const float*)d_in[6];
    const float* l0_b1 = (const float*)d_in[7];
    const float* l0_w2 = (const float*)d_in[8];
    const float* l0_b2 = (const float*)d_in[9];
    const float* ew    = (const float*)d_in[10];
    const float* eb    = (const float*)d_in[11];
    const float* w1    = (const float*)d_in[12];
    const float* b1    = (const float*)d_in[13];
    const float* w2    = (const float*)d_in[14];
    const float* b2    = (const float*)d_in[15];
    const float* gam   = (const float*)d_in[16];
    const float* bet   = (const float*)d_in[17];
    const float* hw1   = (const float*)d_in[18];
    const float* hb1   = (const float*)d_in[19];
    const float* hw2   = (const float*)d_in[20];
    const float* hb2   = (const float*)d_in[21];
    float* out = (float*)d_out;

    float *hp, *aggp, *statsp, *scp, *sfp, *poolp, *cntp;
    int *curp, *posp;
    __half *projp;
    cudaGetSymbolAddress((void**)&hp, g_h);
    cudaGetSymbolAddress((void**)&aggp, g_agg);
    cudaGetSymbolAddress((void**)&projp, g_proj);
    cudaGetSymbolAddress((void**)&statsp, g_stats);
    cudaGetSymbolAddress((void**)&scp, g_bnsc);
    cudaGetSymbolAddress((void**)&sfp, g_bnsf);
    cudaGetSymbolAddress((void**)&poolp, g_pool);
    cudaGetSymbolAddress((void**)&cntp, g_cnt);
    cudaGetSymbolAddress((void**)&curp, g_cur);
    cudaGetSymbolAddress((void**)&posp, g_pos);

    cudaMemsetAsync(curp, 0, NN * sizeof(int));
    cudaMemsetAsync(statsp, 0, 4 * 2 * HH * sizeof(float));
    cudaMemsetAsync(poolp, 0, GG * HH * sizeof(float));
    cudaMemsetAsync(cntp, 0, GG * sizeof(float));

    hist_kernel<<<(EE + 255) / 256, 256>>>(eidx);
    scan_kernel<<<1, 1024>>>();
    scatter_kernel<<<(EE + 255) / 256, 256>>>(eidx);

    // layer 0
    eproj_kernel<32><<<EPROJ_BLOCKS, 256>>>(ea, posp, l0_ew, l0_eb, projp);
    agg32_kernel<<<AGG_BLOCKS, 256>>>(x, projp, aggp);
    gemm_fused_kernel<32><<<(NN + 63) / 64, 256>>>(aggp, l0_w1, l0_b1, l0_w2, l0_b2, hp, statsp);
    bn_coef_kernel<<<1, 64>>>(statsp, gam, bet, scp, sfp);

    // layers 1..3
    for (int i = 1; i < 4; i++) {
        eproj_kernel<64><<<EPROJ_BLOCKS, 256>>>(ea, posp, ew + (i - 1) * HH * 16,
                                                eb + (i - 1) * HH, projp);
        agg64_kernel<<<AGG_BLOCKS, 256>>>(hp, (const __half2*)projp,
                                          scp + (i - 1) * HH, sfp + (i - 1) * HH, aggp);
        gemm_fused_kernel<64><<<(NN + 63) / 64, 256>>>(aggp, w1 + (i - 1) * HH * HH,
                                                       b1 + (i - 1) * HH,
                                                       w2 + (i - 1) * HH * HH,
                                                       b2 + (i - 1) * HH, hp,
                                                       statsp + i * 2 * HH);
        bn_coef_kernel<<<1, 64>>>(statsp + i * 2 * HH, gam + i * HH, bet + i * HH,
                                  scp + i * HH, sfp + i * HH);
    }

    pool_kernel<<<(NN + 255) / 256, 256>>>(hp, batch, scp + 3 * HH, sfp + 3 * HH);
    head_kernel<<<GG, 128>>>(hw1, hb1, hw2, hb2, out);
}

// round 8
// speedup vs baseline: 1.8081x; 1.8081x over previous
#include <cuda_runtime.h>
#include <cuda_fp16.h>
#include <cstdint>

#define NN 100000
#define EE 1600000
#define DIN_ 32
#define HH 64
#define GG 128
#define OUTC 10

#define AGG_BLOCKS 592
#define AGG_WPB 8
#define AGG_WARPS (AGG_BLOCKS * AGG_WPB)                 // 4736
#define AGG_NPER ((NN + AGG_WARPS - 1) / AGG_WARPS)      // 22

#define EP_BLOCKS 592
#define EP_WARPS (EP_BLOCKS * 8)                          // 4736
#define EP_EPW ((EE + EP_WARPS - 1) / EP_WARPS)           // 338

typedef unsigned long long u64;
typedef unsigned int u32;

// ---------------- scratch ----------------
__device__ float  g_h [(size_t)NN * HH];      // layer output (pre-BN "hraw")
__device__ float  g_agg[(size_t)NN * HH];
__device__ __half g_proj[(size_t)EE * 64];    // per-layer edge projection (CSR order)
__device__ int    g_srcs[EE];                 // src permuted to CSR order
__device__ int    g_pos[EE];                  // original edge -> CSR position
__device__ int    g_rowptr[NN + 1];
__device__ int    g_cur[NN];
__device__ float  g_stats[4 * 2 * HH];
__device__ float  g_bnsc[4 * HH];
__device__ float  g_bnsf[4 * HH];
__device__ float  g_pool[GG * HH];
__device__ float  g_cnt[GG];

// ---------------- f32x2 helpers ----------------
__device__ __forceinline__ u64 ffma2(u64 a, u64 b, u64 c) {
    u64 d; asm("fma.rn.f32x2 %0, %1, %2, %3;" : "=l"(d) : "l"(a), "l"(b), "l"(c)); return d;
}
__device__ __forceinline__ u64 fmul2(u64 a, u64 b) {
    u64 d; asm("mul.rn.f32x2 %0, %1, %2;" : "=l"(d) : "l"(a), "l"(b)); return d;
}
__device__ __forceinline__ void unpk2(u64 v, float& lo, float& hi) {
    asm("mov.b64 {%0, %1}, %2;" : "=f"(lo), "=f"(hi) : "l"(v));
}

// ---------------- cp.async helpers ----------------
__device__ __forceinline__ void cp_async16(u32 saddr, const void* gaddr, int pred) {
    asm volatile(
        "{\n\t.reg .pred p;\n\tsetp.ne.b32 p, %2, 0;\n\t"
        "@p cp.async.ca.shared.global [%0], [%1], 16;\n\t}"
        :: "r"(saddr), "l"(gaddr), "r"(pred) : "memory");
}
#define CP_COMMIT() asm volatile("cp.async.commit_group;" ::: "memory")
#define CP_WAIT1()  asm volatile("cp.async.wait_group 1;" ::: "memory")
#define CP_WAIT0()  asm volatile("cp.async.wait_group 0;" ::: "memory")

// ---------------- CSR build ----------------
__global__ void hist_kernel(const int* __restrict__ eidx) {
    int e = blockIdx.x * blockDim.x + threadIdx.x;
    if (e < EE) atomicAdd(&g_cur[eidx[EE + e]], 1);
}

__global__ void __launch_bounds__(1024) scan_kernel() {
    int t = threadIdx.x;
    int sum = 0;
    if (t < 1000) {
        const int4* p = (const int4*)(g_cur + t * 100);
#pragma unroll 5
        for (int q = 0; q < 25; q++) { int4 v = p[q]; sum += v.x + v.y + v.z + v.w; }
    }
    int lane = t & 31, wid = t >> 5;
    int inc = sum;
#pragma unroll
    for (int d = 1; d < 32; d <<= 1) {
        int n = __shfl_up_sync(0xffffffffu, inc, d);
        if (lane >= d) inc += n;
    }
    __shared__ int wsum[32];
    if (lane == 31) wsum[wid] = inc;
    __syncthreads();
    if (wid == 0) {
        int wv = wsum[lane];
        int winc = wv;
#pragma unroll
        for (int d = 1; d < 32; d <<= 1) {
            int n = __shfl_up_sync(0xffffffffu, winc, d);
            if (lane >= d) winc += n;
        }
        wsum[lane] = winc - wv;
    }
    __syncthreads();
    if (t < 1000) {
        int run = inc - sum + wsum[wid];
        const int4* p = (const int4*)(g_cur + t * 100);
#pragma unroll 5
        for (int q = 0; q < 25; q++) {
            int4 v = p[q];
            int i = t * 100 + q * 4;
            int4 r; r.x = run; run += v.x; r.y = run; run += v.y;
            r.z = run; run += v.z; r.w = run; run += v.w;
            *(int4*)(g_rowptr + i) = r;
            *(int4*)(g_cur + i) = r;
        }
    }
    if (t == 1023) g_rowptr[NN] = EE;
}

__global__ void scatter_kernel(const int* __restrict__ eidx) {
    int e = blockIdx.x * blockDim.x + threadIdx.x;
    if (e >= EE) return;
    int d = eidx[EE + e];
    int pos = atomicAdd(&g_cur[d], 1);
    g_srcs[pos] = eidx[e];
    g_pos[e] = pos;
}

// ---------------- edge projection: proj[pos[e]] = ea[e] @ ew^T + eb (fp16 rows) ----
// warp streams contiguous edges; lane owns channel(-pair); one coalesced full-line
// store per edge row at its CSR position.
template <int C>
__global__ void __launch_bounds__(256) eproj_kernel(
    const float* __restrict__ ea, const int* __restrict__ posv,
    const float* __restrict__ ew, const float* __restrict__ ebv,
    __half* __restrict__ proj)
{
    __shared__ __align__(16) float sattr[8][2][128];
    int wip = threadIdx.x >> 5, lane = threadIdx.x & 31;
    int w = blockIdx.x * 8 + wip;
    int ebeg = w * EP_EPW;
    if (ebeg >= EE) return;
    int eend = ebeg + EP_EPW; if (eend > EE) eend = EE;

    // weights in registers
    u64 W0[8], W1[8];
    float eb0, eb1;
    if (C == 64) {
        const ulonglong2* wp = (const ulonglong2*)(ew + (lane * 2) * 16);
#pragma unroll
        for (int q = 0; q < 4; q++) {
            ulonglong2 v0 = wp[q];     W0[2*q] = v0.x; W0[2*q+1] = v0.y;
            ulonglong2 v1 = wp[q + 4]; W1[2*q] = v1.x; W1[2*q+1] = v1.y;
        }
        eb0 = ebv[lane * 2]; eb1 = ebv[lane * 2 + 1];
    } else {
        const ulonglong2* wp = (const ulonglong2*)(ew + lane * 16);
#pragma unroll
        for (int q = 0; q < 4; q++) { ulonglong2 v = wp[q]; W0[2*q] = v.x; W0[2*q+1] = v.y; }
        eb0 = ebv[lane]; eb1 = 0.f;
    }

    u32 sb0 = (u32)__cvta_generic_to_shared(&sattr[wip][0][0]);
    u32 sb1 = (u32)__cvta_generic_to_shared(&sattr[wip][1][0]);

    int j0 = ebeg;
    int m0 = eend - j0; if (m0 > 8) m0 = 8;
    cp_async16(sb0 + lane * 16, ea + (size_t)j0 * 16 + lane * 4, lane < 4 * m0);
    CP_COMMIT();

    int b = 0;
    while (j0 < eend) {
        int j1 = j0 + 8;
        int m1 = eend - j1; if (m1 > 8) m1 = 8;
        cp_async16((b ? sb0 : sb1) + lane * 16,
                   ea + (size_t)j1 * 16 + lane * 4, lane < 4 * m1);
        CP_COMMIT();
        CP_WAIT1();
        __syncwarp();
        const float* cb = b ? &sattr[wip][1][0] : &sattr[wip][0][0];
#pragma unroll
        for (int e = 0; e < 8; e++) {
            if (e < m0) {
                const ulonglong2* ap = (const ulonglong2*)(cb + e * 16);
                ulonglong2 q0 = ap[0], q1 = ap[1], q2 = ap[2], q3 = ap[3];
                int p = __ldg(posv + j0 + e);          // uniform
                if (C == 64) {
                    // 4 chains of 4 for ILP
                    u64 aA0 = fmul2(q0.x, W0[0]);
                    u64 aB0 = fmul2(q2.x, W0[4]);
                    u64 aA1 = fmul2(q0.x, W1[0]);
                    u64 aB1 = fmul2(q2.x, W1[4]);
                    aA0 = ffma2(q0.y, W0[1], aA0); aA1 = ffma2(q0.y, W1[1], aA1);
                    aB0 = ffma2(q2.y, W0[5], aB0); aB1 = ffma2(q2.y, W1[5], aB1);
                    aA0 = ffma2(q1.x, W0[2], aA0); aA1 = ffma2(q1.x, W1[2], aA1);
                    aB0 = ffma2(q3.x, W0[6], aB0); aB1 = ffma2(q3.x, W1[6], aB1);
                    aA0 = ffma2(q1.y, W0[3], aA0); aA1 = ffma2(q1.y, W1[3], aA1);
                    aB0 = ffma2(q3.y, W0[7], aB0); aB1 = ffma2(q3.y, W1[7], aB1);
                    float lA0, hA0, lB0, hB0, lA1, hA1, lB1, hB1;
                    unpk2(aA0, lA0, hA0); unpk2(aB0, lB0, hB0);
                    unpk2(aA1, lA1, hA1); unpk2(aB1, lB1, hB1);
                    float v0 = lA0 + hA0 + lB0 + hB0 + eb0;
                    float v1 = lA1 + hA1 + lB1 + hB1 + eb1;
                    ((__half2*)proj)[(size_t)p * 32 + lane] = __floats2half2_rn(v0, v1);
                } else {
                    u64 aA = fmul2(q0.x, W0[0]);
                    u64 aB = fmul2(q2.x, W0[4]);
                    aA = ffma2(q0.y, W0[1], aA); aB = ffma2(q2.y, W0[5], aB);
                    aA = ffma2(q1.x, W0[2], aA); aB = ffma2(q3.x, W0[6], aB);
                    aA = ffma2(q1.y, W0[3], aA); aB = ffma2(q3.y, W0[7], aB);
                    float lA, hA, lB, hB;
                    unpk2(aA, lA, hA); unpk2(aB, lB, hB);
                    float v = lA + hA + lB + hB + eb0;
                    proj[(size_t)p * 32 + lane] = __float2half_rn(v);
                }
            }
        }
        __syncwarp();
        j0 = j1; m0 = m1; b ^= 1;
    }
    CP_WAIT0();
}

// ---------------- layer-0 aggregation (C=32): lite streaming ----------------
__global__ void __launch_bounds__(256) agg32_kernel(
    const float* __restrict__ xin, const __half* __restrict__ proj,
    float* __restrict__ agg)
{
    int wip = threadIdx.x >> 5, lane = threadIdx.x & 31;
    int w = blockIdx.x * AGG_WPB + wip;
    int nbeg = w * AGG_NPER;
    if (nbeg >= NN) return;
    int nend = nbeg + AGG_NPER; if (nend > NN) nend = NN;

    int jbeg = g_rowptr[nbeg], jend = g_rowptr[nend];
    int node = nbeg;
    int next_end = g_rowptr[node + 1];
    float self = xin[(size_t)node * 32 + lane];
    float A = 0.f;

    for (int j0 = jbeg; j0 < jend; j0 += 8) {
        int m = jend - j0; if (m > 8) m = 8;
        float xs[8]; __half pr[8];
#pragma unroll
        for (int e = 0; e < 8; e++) {
            if (e < m) {
                int s = g_srcs[j0 + e];
                xs[e] = xin[(size_t)s * 32 + lane];
                pr[e] = proj[(size_t)(j0 + e) * 32 + lane];
            }
        }
#pragma unroll
        for (int e = 0; e < 8; e++) {
            if (e < m) {
                int j = j0 + e;
                while (j >= next_end) {               // uniform across warp
                    agg[(size_t)node * 32 + lane] = self + A;
                    A = 0.f;
                    node++;
                    next_end = g_rowptr[node + 1];
                    self = xin[(size_t)node * 32 + lane];
                }
                A += fmaxf(xs[e] + __half2float(pr[e]), 0.f);
            }
        }
    }
    while (true) {
        agg[(size_t)node * 32 + lane] = self + A;
        A = 0.f;
        node++;
        if (node >= nend) break;
        self = xin[(size_t)node * 32 + lane];
    }
}

// ---------------- layers 1-3 aggregation (C=64, BN+relu folded): lite -------------
__global__ void __launch_bounds__(256) agg64_kernel(
    const float* __restrict__ hraw, const __half2* __restrict__ proj2,
    const float* __restrict__ bnsc, const float* __restrict__ bnsf,
    float* __restrict__ agg)
{
    int wip = threadIdx.x >> 5, lane = threadIdx.x & 31;
    int w = blockIdx.x * AGG_WPB + wip;
    int nbeg = w * AGG_NPER;
    if (nbeg >= NN) return;
    int nend = nbeg + AGG_NPER; if (nend > NN) nend = NN;
    int c0 = lane * 2;
    float sc0 = bnsc[c0], sc1 = bnsc[c0 + 1];
    float sf0 = bnsf[c0], sf1 = bnsf[c0 + 1];

    int jbeg = g_rowptr[nbeg], jend = g_rowptr[nend];
    int node = nbeg;
    int next_end = g_rowptr[node + 1];
    float2 self = *(const float2*)(hraw + (size_t)node * 64 + c0);
    float A0 = 0.f, A1 = 0.f;

    for (int j0 = jbeg; j0 < jend; j0 += 8) {
        int m = jend - j0; if (m > 8) m = 8;
        float2 xs[8]; __half2 pr[8];
#pragma unroll
        for (int e = 0; e < 8; e++) {
            if (e < m) {
                int s = g_srcs[j0 + e];
                xs[e] = *(const float2*)(hraw + (size_t)s * 64 + c0);
                pr[e] = proj2[(size_t)(j0 + e) * 32 + lane];
            }
        }
#pragma unroll
        for (int e = 0; e < 8; e++) {
            if (e < m) {
                int j = j0 + e;
                while (j >= next_end) {               // uniform across warp
                    float2 o;
                    o.x = fmaxf(fmaf(self.x, sc0, sf0), 0.f) + A0;
                    o.y = fmaxf(fmaf(self.y, sc1, sf1), 0.f) + A1;
                    *(float2*)(agg + (size_t)node * 64 + c0) = o;
                    A0 = A1 = 0.f;
                    node++;
                    next_end = g_rowptr[node + 1];
                    self = *(const float2*)(hraw + (size_t)node * 64 + c0);
                }
                float2 p = __half22float2(pr[e]);
                float x0 = fmaxf(fmaf(xs[e].x, sc0, sf0), 0.f);
                float x1 = fmaxf(fmaf(xs[e].y, sc1, sf1), 0.f);
                A0 += fmaxf(x0 + p.x, 0.f);
                A1 += fmaxf(x1 + p.y, 0.f);
            }
        }
    }
    while (true) {
        float2 o;
        o.x = fmaxf(fmaf(self.x, sc0, sf0), 0.f) + A0;
        o.y = fmaxf(fmaf(self.y, sc1, sf1), 0.f) + A1;
        *(float2*)(agg + (size_t)node * 64 + c0) = o;
        A0 = A1 = 0.f;
        node++;
        if (node >= nend) break;
        self = *(const float2*)(hraw + (size_t)node * 64 + c0);
    }
}

// ---------------- fused node MLP + BN stats ----------------
template <int K>
__global__ void __launch_bounds__(256) gemm_fused_kernel(
    const float* __restrict__ in, const float* __restrict__ w1,
    const float* __restrict__ b1, const float* __restrict__ w2,
    const float* __restrict__ b2, float* __restrict__ out,
    float* __restrict__ stats)
{
    __shared__ __align__(16) float a_s[64][K + 4];
    __shared__ __align__(16) float w_s[64][68];
    __shared__ __align__(16) float h_s[64][68];
    constexpr int K4 = K / 4;
    int t = threadIdx.x;
    int n0 = blockIdx.x * 64;
    int tx = t & 15, ty = t >> 4;

    for (int i = t; i < 64 * K4; i += 256) {
        int r = i / K4, c4 = i % K4;
        *(float4*)&w_s[r][c4 * 4] = ((const float4*)w1)[i];
        int n = n0 + r;
        float4 v = (n < NN) ? ((const float4*)in)[(size_t)n * K4 + c4] : make_float4(0.f,0.f,0.f,0.f);
        *(float4*)&a_s[r][c4 * 4] = v;
    }
    __syncthreads();

    {
        u64 acc2[4][4] = {};
#pragma unroll
        for (int k = 0; k < K; k += 4) {
            ulonglong2 a[4], b[4];
#pragma unroll
            for (int i = 0; i < 4; i++) a[i] = *(const ulonglong2*)&a_s[ty * 4 + i][k];
#pragma unroll
            for (int j = 0; j < 4; j++) b[j] = *(const ulonglong2*)&w_s[tx + j * 16][k];
#pragma unroll
            for (int i = 0; i < 4; i++)
#pragma unroll
                for (int j = 0; j < 4; j++)
                    acc2[i][j] = ffma2(a[i].x, b[j].x, ffma2(a[i].y, b[j].y, acc2[i][j]));
        }
#pragma unroll
        for (int j = 0; j < 4; j++) {
            int c = tx + j * 16;
            float bb = b1[c];
#pragma unroll
            for (int i = 0; i < 4; i++) {
                float lo, hi; unpk2(acc2[i][j], lo, hi);
                h_s[ty * 4 + i][c] = fmaxf(lo + hi + bb, 0.f);
            }
        }
    }
    __syncthreads();
    for (int i = t; i < 64 * 16; i += 256) {
        int r = i >> 4, c4 = i & 15;
        *(float4*)&w_s[r][c4 * 4] = ((const float4*)w2)[i];
    }
    __syncthreads();

    float val[4][4];
    {
        u64 acc2[4][4] = {};
#pragma unroll
        for (int k = 0; k < 64; k += 4) {
            ulonglong2 a[4], b[4];
#pragma unroll
            for (int i = 0; i < 4; i++) a[i] = *(const ulonglong2*)&h_s[ty * 4 + i][k];
#pragma unroll
            for (int j = 0; j < 4; j++) b[j] = *(const ulonglong2*)&w_s[tx + j * 16][k];
#pragma unroll
            for (int i = 0; i < 4; i++)
#pragma unroll
                for (int j = 0; j < 4; j++)
                    acc2[i][j] = ffma2(a[i].x, b[j].x, ffma2(a[i].y, b[j].y, acc2[i][j]));
        }
#pragma unroll
        for (int j = 0; j < 4; j++) {
            int c = tx + j * 16;
            float bb = b2[c];
#pragma unroll
            for (int i = 0; i < 4; i++) {
                float lo, hi; unpk2(acc2[i][j], lo, hi);
                val[i][j] = fmaxf(lo + hi + bb, 0.f);
            }
        }
    }
    __syncthreads();

    float* redS = &a_s[0][0];
    float* redQ = &h_s[0][0];
#pragma unroll
    for (int j = 0; j < 4; j++) {
        int c = tx + j * 16;
        float s = 0.f, q = 0.f;
#pragma unroll
        for (int i = 0; i < 4; i++) {
            int n = n0 + ty * 4 + i;
            if (n < NN) {
                float v = val[i][j];
                out[(size_t)n * 64 + c] = v;
                s += v; q = fmaf(v, v, q);
            }
        }
        redS[ty * 64 + c] = s;
        redQ[ty * 64 + c] = q;
    }
    __syncthreads();
    if (t < 64) {
        float S = 0.f, Q = 0.f;
#pragma unroll
        for (int r = 0; r < 16; r++) { S += redS[r * 64 + t]; Q += redQ[r * 64 + t]; }
        atomicAdd(&stats[t], S);
        atomicAdd(&stats[64 + t], Q);
    }
}

// ---------------- BN coefficients ----------------
__global__ void bn_coef_kernel(const float* __restrict__ stats,
                               const float* __restrict__ gamma, const float* __restrict__ beta,
                               float* __restrict__ sc, float* __restrict__ sf) {
    int t = threadIdx.x;
    float mu = stats[t] * (1.0f / NN);
    float var = stats[64 + t] * (1.0f / NN) - mu * mu;
    float inv = rsqrtf(var + 1e-5f);
    float g = gamma[t], b = beta[t];
    sc[t] = inv * g;
    sf[t] = b - mu * inv * g;
}

// ---------------- pool (BN of last layer folded; batch sorted) ----------------
__global__ void pool_kernel(const float* __restrict__ hraw, const int* __restrict__ batch,
                            const float* __restrict__ bnsc, const float* __restrict__ bnsf) {
    int warp = blockIdx.x * (blockDim.x >> 5) + (threadIdx.x >> 5);
    int lane = threadIdx.x & 31;
    int base = warp * 32;
    if (base >= NN) return;
    int end = min(base + 32, NN);
    int c0 = lane * 2;
    float sc0 = bnsc[c0], sc1 = bnsc[c0 + 1];
    float sf0 = bnsf[c0], sf1 = bnsf[c0 + 1];

    int curb = batch[base];
    float a0 = 0.f, a1 = 0.f, cf = 0.f;
    for (int n = base; n < end; n++) {
        int b = batch[n];
        if (b != curb) {
            atomicAdd(&g_pool[curb * 64 + c0], a0);
            atomicAdd(&g_pool[curb * 64 + c0 + 1], a1);
            if (lane == 0) atomicAdd(&g_cnt[curb], cf);
            a0 = a1 = cf = 0.f;
            curb = b;
        }
        float2 v = *(const float2*)(hraw + (size_t)n * 64 + c0);
        a0 += fmaxf(fmaf(v.x, sc0, sf0), 0.f);
        a1 += fmaxf(fmaf(v.y, sc1, sf1), 0.f);
        cf += 1.f;
    }
    atomicAdd(&g_pool[curb * 64 + c0], a0);
    atomicAdd(&g_pool[curb * 64 + c0 + 1], a1);
    if (lane == 0) atomicAdd(&g_cnt[curb], cf);
}

// ---------------- MLP head ----------------
__global__ void head_kernel(const float* __restrict__ hw1, const float* __restrict__ hb1,
                            const float* __restrict__ hw2, const float* __restrict__ hb2,
                            float* __restrict__ out) {
    int g = blockIdx.x, t = threadIdx.x;
    __shared__ float p[64];
    __shared__ float z[128];
    if (t < 64) {
        float c = g_cnt[g];
        p[t] = g_pool[g * 64 + t] / fmaxf(c, 1.0f);
    }
    __syncthreads();
    float s = hb1[t];
#pragma unroll 8
    for (int k = 0; k < 64; k++) s = fmaf(p[k], hw1[t * 64 + k], s);
    z[t] = fmaxf(s, 0.f);
    __syncthreads();
    if (t < OUTC) {
        float s2 = hb2[t];
#pragma unroll 8
        for (int k = 0; k < 128; k++) s2 = fmaf(z[k], hw2[t * 128 + k], s2);
        out[g * OUTC + t] = s2;
    }
}

// ---------------- launch ----------------
extern "C" void kernel_launch(void* const* d_in, const int* in_sizes, int n_in,
                              void* d_out, int out_size) {
    const float* x     = (const float*)d_in[0];
    const int*   eidx  = (const int*)  d_in[1];
    const float* ea    = (const float*)d_in[2];
    const int*   batch = (const int*)  d_in[3];
    const float* l0_ew = (const float*)d_in[4];
    const float* l0_eb = (const float*)d_in[5];
    const float* l0_w1 = (const float*)d_in[6];
    const float* l0_b1 = (const float*)d_in[7];
    const float* l0_w2 = (const float*)d_in[8];
    const float* l0_b2 = (const float*)d_in[9];
    const float* ew    = (const float*)d_in[10];
    const float* eb    = (const float*)d_in[11];
    const float* w1    = (const float*)d_in[12];
    const float* b1    = (const float*)d_in[13];
    const float* w2    = (const float*)d_in[14];
    const float* b2    = (const float*)d_in[15];
    const float* gam   = (const float*)d_in[16];
    const float* bet   = (const float*)d_in[17];
    const float* hw1   = (const float*)d_in[18];
    const float* hb1   = (const float*)d_in[19];
    const float* hw2   = (const float*)d_in[20];
    const float* hb2   = (const float*)d_in[21];
    float* out = (float*)d_out;

    float *hp, *aggp, *statsp, *scp, *sfp, *poolp, *cntp;
    int *curp, *posp;
    __half *projp;
    cudaGetSymbolAddress((void**)&hp, g_h);
    cudaGetSymbolAddress((void**)&aggp, g_agg);
    cudaGetSymbolAddress((void**)&projp, g_proj);
    cudaGetSymbolAddress((void**)&statsp, g_stats);
    cudaGetSymbolAddress((void**)&scp, g_bnsc);
    cudaGetSymbolAddress((void**)&sfp, g_bnsf);
    cudaGetSymbolAddress((void**)&poolp, g_pool);
    cudaGetSymbolAddress((void**)&cntp, g_cnt);
    cudaGetSymbolAddress((void**)&curp, g_cur);
    cudaGetSymbolAddress((void**)&posp, g_pos);

    cudaMemsetAsync(curp, 0, NN * sizeof(int));
    cudaMemsetAsync(statsp, 0, 4 * 2 * HH * sizeof(float));
    cudaMemsetAsync(poolp, 0, GG * HH * sizeof(float));
    cudaMemsetAsync(cntp, 0, GG * sizeof(float));

    hist_kernel<<<(EE + 255) / 256, 256>>>(eidx);
    scan_kernel<<<1, 1024>>>();
    scatter_kernel<<<(EE + 255) / 256, 256>>>(eidx);

    // layer 0
    eproj_kernel<32><<<EP_BLOCKS, 256>>>(ea, posp, l0_ew, l0_eb, projp);
    agg32_kernel<<<AGG_BLOCKS, 256>>>(x, projp, aggp);
    gemm_fused_kernel<32><<<(NN + 63) / 64, 256>>>(aggp, l0_w1, l0_b1, l0_w2, l0_b2, hp, statsp);
    bn_coef_kernel<<<1, 64>>>(statsp, gam, bet, scp, sfp);

    // layers 1..3
    for (int i = 1; i < 4; i++) {
        eproj_kernel<64><<<EP_BLOCKS, 256>>>(ea, posp, ew + (i - 1) * HH * 16,
                                             eb + (i - 1) * HH, projp);
        agg64_kernel<<<AGG_BLOCKS, 256>>>(hp, (const __half2*)projp,
                                          scp + (i - 1) * HH, sfp + (i - 1) * HH, aggp);
        gemm_fused_kernel<64><<<(NN + 63) / 64, 256>>>(aggp, w1 + (i - 1) * HH * HH,
                                                       b1 + (i - 1) * HH,
                                                       w2 + (i - 1) * HH * HH,
                                                       b2 + (i - 1) * HH, hp,
                                                       statsp + i * 2 * HH);
        bn_coef_kernel<<<1, 64>>>(statsp + i * 2 * HH, gam + i * HH, bet + i * HH,
                                  scp + i * HH, sfp + i * HH);
    }

    pool_kernel<<<(NN + 255) / 256, 256>>>(hp, batch, scp + 3 * HH, sfp + 3 * HH);
    head_kernel<<<GG, 128>>>(hw1, hb1, hw2, hb2, out);
}